// round 16
// baseline (speedup 1.0000x reference)
#include <cuda_runtime.h>
#include <cuda_fp16.h>
#include <math.h>

#define BATCH  2
#define CH     512
#define NTOK   4096
#define GROUPS 32
#define CPG    16
#define EPS    1e-6f

#define BK     64       // fp16 K-slab
#define MKPH   72       // fp16 row-major smem pitch (halfs): 64 + 8 pad
#define GT     128      // 4 warps, 2x2 warp grid, 64x64 warp tiles
#define NSTG   3
#define TFH    (128 * MKPH)            // halfs per staged tile
#define SMH    (NSTG * 2 * TFH * 2)    // dyn smem bytes = 110592
#define BP     72                      // bounce tile pitch (halfs)

// ---------------- scratch ----------------
__device__ __half g_ht [(size_t)BATCH * NTOK * CH];   // h^T  [b][n][c]
__device__ __half g_wh [(size_t)4 * CH * CH];         // wq,wk,wv,wo (half)
__device__ __half g_qt [(size_t)BATCH * NTOK * CH];   // q^T [b][nq][c]
__device__ __half g_kt [(size_t)BATCH * NTOK * CH];   // k^T [b][nk][c]
__device__ __half g_vh [(size_t)BATCH * CH * NTOK];   // v   [b][c][nk]
__device__ __half g_sh [(size_t)BATCH * NTOK * NTOK]; // exp-scores [b][nq][nk]
__device__ __half g_aot[(size_t)BATCH * NTOK * CH];   // attn-out^T [b][nq][c]
__device__ float  g_rsum[(size_t)BATCH * NTOK];

// ---------------- GroupNorm -> ht[n][c] fp16 directly (+ rsum zeroing) ----------------
__global__ void gn_kernel(const float* __restrict__ x,
                          const float* __restrict__ gamma,
                          const float* __restrict__ beta)
{
    const int gid = blockIdx.x * blockDim.x + threadIdx.x;
    if (gid < BATCH * NTOK) g_rsum[gid] = 0.f;

    const int bg = blockIdx.x;
    const int b = bg / GROUPS, g = bg % GROUPS;
    const size_t base = ((size_t)b * CH + (size_t)g * CPG) * NTOK;
    const float* xp = x + base;
    __half* htb = g_ht + (size_t)b * NTOK * CH + g * CPG;
    const int M = CPG * NTOK;
    const int t = threadIdx.x;     // 256 threads

    float s = 0.f, s2 = 0.f;
    for (int i = t * 4; i < M; i += 1024) {
        float4 v = *(const float4*)&xp[i];
        s  += v.x + v.y + v.z + v.w;
        s2 += v.x*v.x + v.y*v.y + v.z*v.z + v.w*v.w;
    }
    __shared__ float shs[8], shs2[8];
    __shared__ float shga[CPG], shbe[CPG];
    #pragma unroll
    for (int o = 16; o; o >>= 1) {
        s  += __shfl_xor_sync(0xFFFFFFFFu, s,  o);
        s2 += __shfl_xor_sync(0xFFFFFFFFu, s2, o);
    }
    const int wid = t >> 5, lane = t & 31;
    if (!lane) { shs[wid] = s; shs2[wid] = s2; }
    __syncthreads();
    if (t == 0) {
        float ts = 0.f, ts2 = 0.f;
        #pragma unroll
        for (int i = 0; i < 8; i++) { ts += shs[i]; ts2 += shs2[i]; }
        const float mean = ts / (float)M;
        const float var  = ts2 / (float)M - mean * mean;
        shs[0] = mean;
        shs2[0] = rsqrtf(var + EPS);
    }
    __syncthreads();
    if (t < CPG) {
        const float ga = gamma[g * CPG + t] * shs2[0];
        shga[t] = ga;
        shbe[t] = beta[g * CPG + t] - shs[0] * ga;
    }
    __syncthreads();

    __shared__ float tile[CPG][257];
    for (int n0 = 0; n0 < NTOK; n0 += 256) {
        #pragma unroll
        for (int c = 0; c < CPG; c++)
            tile[c][t] = xp[(size_t)c * NTOK + n0 + t] * shga[c] + shbe[c];
        __syncthreads();
        __half hv[CPG];
        #pragma unroll
        for (int c = 0; c < CPG; c++) hv[c] = __float2half_rn(tile[c][t]);
        *(uint4*)&htb[(size_t)(n0 + t) * CH] = *(uint4*)hv;
        *(uint4*)&htb[(size_t)(n0 + t) * CH + 8] = *(uint4*)(hv + 8);
        __syncthreads();
    }
}

// ---------------- weight fp32 -> fp16 ----------------
struct W4 { const float* w[4]; };
__global__ void cvt_w(W4 ws)
{
    const size_t i = (size_t)blockIdx.x * blockDim.x + threadIdx.x;
    const int wsel = (int)(i >> 18);
    const int idx  = (int)(i & 262143);
    g_wh[i] = __float2half_rn(ws.w[wsel][idx]);
}

// ---------------- cp.async staging (fp16, 128 rows x 64 halfs) ----------------
__device__ __forceinline__ void cpa16h(__half* dst, const __half* src)
{
    unsigned s = (unsigned)__cvta_generic_to_shared(dst);
    asm volatile("cp.async.cg.shared.global [%0], [%1], 16;" :: "r"(s), "l"(src));
}
__device__ __forceinline__ void stage_h(__half* dst, const __half* src, int ld, int tid)
{
    #pragma unroll
    for (int i = 0; i < 8; i++) {
        const int c = tid + (i << 7);
        const int row = c >> 3, k8 = (c & 7) << 3;
        cpa16h(dst + row * MKPH + k8, src + (size_t)row * ld + k8);
    }
}

__device__ __forceinline__ void ldsm4(unsigned& r0, unsigned& r1,
                                      unsigned& r2, unsigned& r3, unsigned addr)
{
    asm volatile("ldmatrix.sync.aligned.m8n8.x4.shared.b16 {%0,%1,%2,%3}, [%4];"
                 : "=r"(r0), "=r"(r1), "=r"(r2), "=r"(r3) : "r"(addr));
}

// ================= fp16 tensor-core GEMM =================
// C[m,n] = scale * (sum_k A[m,k]*B[n,k]) + bias[m]  [exp + rowsum[m]] [/ rsum[n]]
// omode: 0 = fp32 [m][n] (+resid), 1 = half [m][n], 2 = half transposed [n][m]
template<bool DO_EXP, bool COLSCALE>
__device__ __forceinline__
void gemmh_body(const __half* __restrict__ A,
                const __half* __restrict__ Bm,
                void* __restrict__ Cv,
                const float* __restrict__ bias,
                const float* __restrict__ resid,
                float* __restrict__ rsum,
                int K, int lda, int ldb, int ldc,
                float scale, int omode, int m0, int n0)
{
    extern __shared__ __half dynh[];
    __half* SA = dynh;
    __half* SB = dynh + NSTG * TFH;

    const int tid = threadIdx.x;
    const int warp = tid >> 5, lane = tid & 31;
    const int wm = (warp >> 1) * 64;
    const int wn = (warp & 1) * 64;
    const int grp = lane >> 2;
    const int tig = lane & 3;

    const __half* At = A + (size_t)m0 * lda;
    const __half* Bt = Bm + (size_t)n0 * ldb;
    const int nslab = K / BK;

    // ldmatrix per-lane base offsets (bytes within a tile)
    const unsigned sbase = (unsigned)__cvta_generic_to_shared(dynh);
    unsigned aoff[4], boff[4];
    {
        const int arow = lane & 15, asel = lane >> 4;           // A: rows m..m+15, k half-sel
        #pragma unroll
        for (int mi = 0; mi < 4; mi++)
            aoff[mi] = (unsigned)(((wm + mi * 16 + arow) * MKPH + asel * 8) * 2);
        const int brow = ((lane >> 4) << 3) + (lane & 7);        // B: n row within 16
        const int bsel = (lane >> 3) & 1;                        // k half-sel
        #pragma unroll
        for (int pj = 0; pj < 4; pj++)
            boff[pj] = (unsigned)(((wn + pj * 16 + brow) * MKPH + bsel * 8) * 2);
    }

    stage_h(SA, At, lda, tid);
    stage_h(SB, Bt, ldb, tid);
    asm volatile("cp.async.commit_group;");
    if (1 < nslab) {
        stage_h(SA + TFH, At + BK, lda, tid);
        stage_h(SB + TFH, Bt + BK, ldb, tid);
        asm volatile("cp.async.commit_group;");
    }

    float acc[4][8][4];
    #pragma unroll
    for (int a = 0; a < 4; a++)
        #pragma unroll
        for (int b = 0; b < 8; b++)
            #pragma unroll
            for (int c = 0; c < 4; c++) acc[a][b][c] = 0.f;

    unsigned af[2][4][4], bf[2][8][2];

    int buf = 0;
    for (int s = 0; s < nslab; s++) {
        if (s + 1 < nslab) asm volatile("cp.async.wait_group 1;");
        else               asm volatile("cp.async.wait_group 0;");
        __syncthreads();

        if (s + 2 < nslab) {
            const int nb = (buf + 2 >= NSTG) ? (buf + 2 - NSTG) : (buf + 2);
            stage_h(SA + nb * TFH, At + (size_t)(s + 2) * BK, lda, tid);
            stage_h(SB + nb * TFH, Bt + (size_t)(s + 2) * BK, ldb, tid);
            asm volatile("cp.async.commit_group;");
        }

        const unsigned sab = sbase + (unsigned)(buf * TFH * 2);
        const unsigned sbb = sbase + (unsigned)((NSTG + buf) * TFH * 2);

        auto ldfr = [&](int p, int kc) {
            const unsigned ka = sab + (unsigned)(kc * 2);
            const unsigned kb = sbb + (unsigned)(kc * 2);
            #pragma unroll
            for (int mi = 0; mi < 4; mi++)
                ldsm4(af[p][mi][0], af[p][mi][1], af[p][mi][2], af[p][mi][3],
                      ka + aoff[mi]);
            #pragma unroll
            for (int pj = 0; pj < 4; pj++)
                ldsm4(bf[p][2 * pj][0], bf[p][2 * pj][1],
                      bf[p][2 * pj + 1][0], bf[p][2 * pj + 1][1],
                      kb + boff[pj]);
        };

        ldfr(0, 0);
        #pragma unroll
        for (int kc = 0; kc < BK; kc += 16) {
            const int p = (kc >> 4) & 1;
            if (kc + 16 < BK) ldfr(p ^ 1, kc + 16);
            #pragma unroll
            for (int mi = 0; mi < 4; mi++)
                #pragma unroll
                for (int nj = 0; nj < 8; nj++) {
                    asm volatile(
                        "mma.sync.aligned.m16n8k16.row.col.f32.f16.f16.f32 "
                        "{%0,%1,%2,%3}, {%4,%5,%6,%7}, {%8,%9}, {%0,%1,%2,%3};"
                        : "+f"(acc[mi][nj][0]), "+f"(acc[mi][nj][1]),
                          "+f"(acc[mi][nj][2]), "+f"(acc[mi][nj][3])
                        : "r"(af[p][mi][0]), "r"(af[p][mi][1]),
                          "r"(af[p][mi][2]), "r"(af[p][mi][3]),
                          "r"(bf[p][nj][0]), "r"(bf[p][nj][1]));
                }
        }
        buf = (buf + 1 >= NSTG) ? 0 : buf + 1;
    }

    // ---- epilogue
    float inv[8][2];
    if (COLSCALE) {
        #pragma unroll
        for (int nj = 0; nj < 8; nj++) {
            const int n = n0 + wn + nj * 8 + (tig << 1);
            inv[nj][0] = 1.f / rsum[n];
            inv[nj][1] = 1.f / rsum[n + 1];
        }
    }
    float rsA[4], rsB[4];
    #pragma unroll
    for (int mi = 0; mi < 4; mi++) { rsA[mi] = 0.f; rsB[mi] = 0.f; }

    if (omode == 0) {
        #pragma unroll
        for (int mi = 0; mi < 4; mi++) {
            const int mA = m0 + wm + mi * 16 + grp;
            const int mB = mA + 8;
            const float bvA = bias ? bias[mA] : 0.f;
            const float bvB = bias ? bias[mB] : 0.f;
            #pragma unroll
            for (int nj = 0; nj < 8; nj++) {
                const int n = n0 + wn + nj * 8 + (tig << 1);
                float2 o0, o1;
                o0.x = acc[mi][nj][0] * scale + bvA;
                o0.y = acc[mi][nj][1] * scale + bvA;
                o1.x = acc[mi][nj][2] * scale + bvB;
                o1.y = acc[mi][nj][3] * scale + bvB;
                float* fC = (float*)Cv;
                if (resid) {
                    float2 r0 = *(const float2*)&resid[(size_t)mA * ldc + n];
                    float2 r1 = *(const float2*)&resid[(size_t)mB * ldc + n];
                    o0.x += r0.x; o0.y += r0.y;
                    o1.x += r1.x; o1.y += r1.y;
                }
                *(float2*)&fC[(size_t)mA * ldc + n] = o0;
                *(float2*)&fC[(size_t)mB * ldc + n] = o1;
            }
        }
    } else {
        // half outputs: smem-bounce for coalesced 16B stores
        __syncthreads();   // staged slabs drained; smem reuse safe
        __half* tile = dynh + warp * (64 * BP);
        #pragma unroll
        for (int mi = 0; mi < 4; mi++) {
            const int lm = mi * 16 + grp;
            const int mA = m0 + wm + lm;
            const float bvA = bias ? bias[mA] : 0.f;
            const float bvB = bias ? bias[mA + 8] : 0.f;
            #pragma unroll
            for (int nj = 0; nj < 8; nj++) {
                const int lnj = nj * 8 + (tig << 1);
                float2 o0, o1;
                o0.x = acc[mi][nj][0] * scale + bvA;
                o0.y = acc[mi][nj][1] * scale + bvA;
                o1.x = acc[mi][nj][2] * scale + bvB;
                o1.y = acc[mi][nj][3] * scale + bvB;
                if (DO_EXP) {
                    o0.x = __expf(o0.x); o0.y = __expf(o0.y);
                    o1.x = __expf(o1.x); o1.y = __expf(o1.y);
                    rsA[mi] += o0.x + o0.y;
                    rsB[mi] += o1.x + o1.y;
                }
                if (COLSCALE) {
                    o0.x *= inv[nj][0]; o0.y *= inv[nj][1];
                    o1.x *= inv[nj][0]; o1.y *= inv[nj][1];
                }
                if (omode == 1) {
                    *(__half2*)&tile[lm * BP + lnj]       = __floats2half2_rn(o0.x, o0.y);
                    *(__half2*)&tile[(lm + 8) * BP + lnj] = __floats2half2_rn(o1.x, o1.y);
                } else {
                    tile[lnj * BP + lm]           = __float2half_rn(o0.x);
                    tile[(lnj + 1) * BP + lm]     = __float2half_rn(o0.y);
                    tile[lnj * BP + lm + 8]       = __float2half_rn(o1.x);
                    tile[(lnj + 1) * BP + lm + 8] = __float2half_rn(o1.y);
                }
            }
        }
        __syncwarp();
        const int orow = (omode == 1) ? (m0 + wm) : (n0 + wn);
        const int ocol = (omode == 1) ? (n0 + wn) : (m0 + wm);
        __half* hC = (__half*)Cv;
        #pragma unroll
        for (int it = 0; it < 16; it++) {
            const int idx = it * 32 + lane;
            const int r = idx >> 3, seg = idx & 7;
            uint4 v = *(uint4*)&tile[r * BP + seg * 8];
            *(uint4*)&hC[(size_t)(orow + r) * ldc + ocol + seg * 8] = v;
        }
    }

    if (DO_EXP) {
        #pragma unroll
        for (int mi = 0; mi < 4; mi++) {
            float a = rsA[mi], b = rsB[mi];
            a += __shfl_xor_sync(0xFFFFFFFFu, a, 1);
            a += __shfl_xor_sync(0xFFFFFFFFu, a, 2);
            b += __shfl_xor_sync(0xFFFFFFFFu, b, 1);
            b += __shfl_xor_sync(0xFFFFFFFFu, b, 2);
            if (tig == 0) {
                const int mA = m0 + wm + mi * 16 + grp;
                atomicAdd(&rsum[mA], a);
                atomicAdd(&rsum[mA + 8], b);
            }
        }
    }
}

template<bool DO_EXP, bool COLSCALE>
__global__ __launch_bounds__(GT, 2)
void gemm_h(const __half* __restrict__ A,  size_t sAb,
            const __half* __restrict__ Bm, size_t sBb,
            void* __restrict__ Cv,         size_t sCb,
            const float* __restrict__ bias,
            const float* __restrict__ resid, size_t sRb,
            float* rsum,
            int K, int lda, int ldb, int ldc, float scale, int omode)
{
    const int bz = blockIdx.z;
    char* Cb = (char*)Cv + sCb * (omode == 0 ? 4 : 2) * bz;
    gemmh_body<DO_EXP, COLSCALE>(
        A + sAb * bz, Bm + sBb * bz, (void*)Cb,
        bias, resid ? resid + sRb * bz : nullptr,
        rsum ? rsum + (size_t)NTOK * bz : nullptr,
        K, lda, ldb, ldc, scale, omode,
        blockIdx.y * 128, blockIdx.x * 128);
}

struct QKVH {
    const __half* w[3];
    const float*  b[3];
    __half*       o[3];
    int           ldc[3];
    int           omode[3];
    size_t        ostride[3];
};

__global__ __launch_bounds__(GT, 2)
void qkv_h(QKVH a, const __half* __restrict__ ht)
{
    const int pj = blockIdx.z / BATCH;
    const int bz = blockIdx.z % BATCH;
    const size_t sNC = (size_t)NTOK * CH;
    gemmh_body<false, false>(
        a.w[pj], ht + sNC * bz, (void*)(a.o[pj] + a.ostride[pj] * bz),
        a.b[pj], nullptr, nullptr,
        CH, CH, CH, a.ldc[pj], 1.f, a.omode[pj],
        blockIdx.y * 128, blockIdx.x * 128);
}

// ---------------- launcher ----------------
extern "C" void kernel_launch(void* const* d_in, const int* in_sizes, int n_in,
                              void* d_out, int out_size)
{
    const float* x     = (const float*)d_in[0];
    const float* gamma = (const float*)d_in[1];
    const float* beta  = (const float*)d_in[2];
    const float* wq    = (const float*)d_in[3];
    const float* bq    = (const float*)d_in[4];
    const float* wk    = (const float*)d_in[5];
    const float* bk    = (const float*)d_in[6];
    const float* wv    = (const float*)d_in[7];
    const float* bv    = (const float*)d_in[8];
    const float* wo    = (const float*)d_in[9];
    const float* bo    = (const float*)d_in[10];
    float* out = (float*)d_out;

    float *rsum;
    __half *ht, *wh, *qt, *kt, *vh, *sh, *aot;
    cudaGetSymbolAddress((void**)&ht,   g_ht);
    cudaGetSymbolAddress((void**)&wh,   g_wh);
    cudaGetSymbolAddress((void**)&qt,   g_qt);
    cudaGetSymbolAddress((void**)&kt,   g_kt);
    cudaGetSymbolAddress((void**)&vh,   g_vh);
    cudaGetSymbolAddress((void**)&sh,   g_sh);
    cudaGetSymbolAddress((void**)&aot,  g_aot);
    cudaGetSymbolAddress((void**)&rsum, g_rsum);

    const size_t sNC = (size_t)NTOK * CH;
    const size_t sNN = (size_t)NTOK * NTOK;
    const size_t sCN = (size_t)CH * NTOK;
    const size_t WSZ = (size_t)CH * CH;
    const float attn_scale = 0.044194173824159216f;   // 512^-0.5

    static bool attr_done = false;
    if (!attr_done) {
        cudaFuncSetAttribute(qkv_h, cudaFuncAttributeMaxDynamicSharedMemorySize, SMH);
        cudaFuncSetAttribute(gemm_h<true, false>,
                             cudaFuncAttributeMaxDynamicSharedMemorySize, SMH);
        cudaFuncSetAttribute(gemm_h<false, true>,
                             cudaFuncAttributeMaxDynamicSharedMemorySize, SMH);
        cudaFuncSetAttribute(gemm_h<false, false>,
                             cudaFuncAttributeMaxDynamicSharedMemorySize, SMH);
        attr_done = true;
    }

    // 1) GroupNorm -> ht (fp16, transposed), zero rsum
    gn_kernel<<<BATCH * GROUPS, 256>>>(x, gamma, beta);

    // 2) weights -> half
    W4 ws; ws.w[0] = wq; ws.w[1] = wk; ws.w[2] = wv; ws.w[3] = wo;
    cvt_w<<<(int)(4 * WSZ / 256), 256>>>(ws);

    // 3) Q/K/V projections (fp16): q^T, k^T transposed; v normal
    QKVH qa;
    qa.w[0] = wh;           qa.w[1] = wh + WSZ;      qa.w[2] = wh + 2 * WSZ;
    qa.b[0] = bq;           qa.b[1] = bk;            qa.b[2] = bv;
    qa.o[0] = qt;           qa.o[1] = kt;            qa.o[2] = vh;
    qa.ldc[0] = CH;         qa.ldc[1] = CH;          qa.ldc[2] = NTOK;
    qa.omode[0] = 2;        qa.omode[1] = 2;         qa.omode[2] = 1;
    qa.ostride[0] = sNC;    qa.ostride[1] = sNC;     qa.ostride[2] = sCN;
    qkv_h<<<dim3(NTOK / 128, CH / 128, 3 * BATCH), GT, SMH>>>(qa, ht);

    // 4) exp-scores: s[nq][nk] = exp(scale * q^T·k), rowsum[nq]
    gemm_h<true, false><<<dim3(NTOK / 128, NTOK / 128, BATCH), GT, SMH>>>(
        qt, sNC, kt, sNC, sh, sNN, nullptr, nullptr, 0, rsum,
        CH, CH, CH, NTOK, attn_scale, 1);

    // 5) ao^T[nq][c] = (v·s^T)/rsum[nq]   (transposed half out)
    gemm_h<false, true><<<dim3(NTOK / 128, CH / 128, BATCH), GT, SMH>>>(
        vh, sCN, sh, sNN, aot, sNC, nullptr, nullptr, 0, rsum,
        NTOK, NTOK, NTOK, CH, 1.f, 2);

    // 6) out = x + wo·ao + bo  (fp32 out + residual)
    gemm_h<false, false><<<dim3(NTOK / 128, CH / 128, BATCH), GT, SMH>>>(
        wh + 3 * WSZ, 0, aot, sNC, out, sCN, bo, x, sCN, nullptr,
        CH, CH, CH, NTOK, 1.f, 0);
}

// round 17
// speedup vs baseline: 1.0491x; 1.0491x over previous
#include <cuda_runtime.h>
#include <cuda_fp16.h>
#include <math.h>

#define BATCH  2
#define CH     512
#define NTOK   4096
#define GROUPS 32
#define CPG    16
#define EPS    1e-6f

#define BK     64       // fp16 K-slab
#define MKPH   72       // fp16 row-major smem pitch (halfs): 64 + 8 pad
#define GT     128      // 4 warps, 2x2 warp grid, 64x64 warp tiles
#define TFH    (128 * MKPH)            // halfs per staged tile
#define SMH3   (3 * 2 * TFH * 2)       // 110592 B (3-stage kernels)
#define SMH2   (2 * 2 * TFH * 2)       // 73728 B  (2-stage scores kernel)
#define BP     72                      // bounce tile pitch (halfs)

// ---------------- scratch ----------------
__device__ __half g_ht [(size_t)BATCH * NTOK * CH];   // h^T  [b][n][c]
__device__ __half g_wh [(size_t)4 * CH * CH];         // wq,wk,wv,wo (half)
__device__ __half g_qt [(size_t)BATCH * NTOK * CH];   // q^T [b][nq][c]
__device__ __half g_kt [(size_t)BATCH * NTOK * CH];   // k^T [b][nk][c]
__device__ __half g_vh [(size_t)BATCH * CH * NTOK];   // v   [b][c][nk]
__device__ __half g_sh [(size_t)BATCH * NTOK * NTOK]; // exp-scores [b][nq][nk]
__device__ __half g_aot[(size_t)BATCH * NTOK * CH];   // attn-out^T [b][nq][c]
__device__ float  g_rsum[(size_t)BATCH * NTOK];

// ---------------- GroupNorm -> ht[n][c] fp16 directly (+ rsum zeroing) ----------------
__global__ void gn_kernel(const float* __restrict__ x,
                          const float* __restrict__ gamma,
                          const float* __restrict__ beta)
{
    const int gid = blockIdx.x * blockDim.x + threadIdx.x;
    if (gid < BATCH * NTOK) g_rsum[gid] = 0.f;

    const int bg = blockIdx.x;
    const int b = bg / GROUPS, g = bg % GROUPS;
    const size_t base = ((size_t)b * CH + (size_t)g * CPG) * NTOK;
    const float* xp = x + base;
    __half* htb = g_ht + (size_t)b * NTOK * CH + g * CPG;
    const int M = CPG * NTOK;
    const int t = threadIdx.x;     // 256 threads

    float s = 0.f, s2 = 0.f;
    for (int i = t * 4; i < M; i += 1024) {
        float4 v = *(const float4*)&xp[i];
        s  += v.x + v.y + v.z + v.w;
        s2 += v.x*v.x + v.y*v.y + v.z*v.z + v.w*v.w;
    }
    __shared__ float shs[8], shs2[8];
    __shared__ float shga[CPG], shbe[CPG];
    #pragma unroll
    for (int o = 16; o; o >>= 1) {
        s  += __shfl_xor_sync(0xFFFFFFFFu, s,  o);
        s2 += __shfl_xor_sync(0xFFFFFFFFu, s2, o);
    }
    const int wid = t >> 5, lane = t & 31;
    if (!lane) { shs[wid] = s; shs2[wid] = s2; }
    __syncthreads();
    if (t == 0) {
        float ts = 0.f, ts2 = 0.f;
        #pragma unroll
        for (int i = 0; i < 8; i++) { ts += shs[i]; ts2 += shs2[i]; }
        const float mean = ts / (float)M;
        const float var  = ts2 / (float)M - mean * mean;
        shs[0] = mean;
        shs2[0] = rsqrtf(var + EPS);
    }
    __syncthreads();
    if (t < CPG) {
        const float ga = gamma[g * CPG + t] * shs2[0];
        shga[t] = ga;
        shbe[t] = beta[g * CPG + t] - shs[0] * ga;
    }
    __syncthreads();

    __shared__ float tile[CPG][257];
    for (int n0 = 0; n0 < NTOK; n0 += 256) {
        #pragma unroll
        for (int c = 0; c < CPG; c++)
            tile[c][t] = xp[(size_t)c * NTOK + n0 + t] * shga[c] + shbe[c];
        __syncthreads();
        __half hv[CPG];
        #pragma unroll
        for (int c = 0; c < CPG; c++) hv[c] = __float2half_rn(tile[c][t]);
        *(uint4*)&htb[(size_t)(n0 + t) * CH] = *(uint4*)hv;
        *(uint4*)&htb[(size_t)(n0 + t) * CH + 8] = *(uint4*)(hv + 8);
        __syncthreads();
    }
}

// ---------------- weight fp32 -> fp16 ----------------
struct W4 { const float* w[4]; };
__global__ void cvt_w(W4 ws)
{
    const size_t i = (size_t)blockIdx.x * blockDim.x + threadIdx.x;
    const int wsel = (int)(i >> 18);
    const int idx  = (int)(i & 262143);
    g_wh[i] = __float2half_rn(ws.w[wsel][idx]);
}

// ---------------- cp.async staging (fp16, 128 rows x 64 halfs) ----------------
__device__ __forceinline__ void cpa16h(__half* dst, const __half* src)
{
    unsigned s = (unsigned)__cvta_generic_to_shared(dst);
    asm volatile("cp.async.cg.shared.global [%0], [%1], 16;" :: "r"(s), "l"(src));
}
__device__ __forceinline__ void stage_h(__half* dst, const __half* src, int ld, int tid)
{
    #pragma unroll
    for (int i = 0; i < 8; i++) {
        const int c = tid + (i << 7);
        const int row = c >> 3, k8 = (c & 7) << 3;
        cpa16h(dst + row * MKPH + k8, src + (size_t)row * ld + k8);
    }
}

__device__ __forceinline__ void ldsm4(unsigned& r0, unsigned& r1,
                                      unsigned& r2, unsigned& r3, unsigned addr)
{
    asm volatile("ldmatrix.sync.aligned.m8n8.x4.shared.b16 {%0,%1,%2,%3}, [%4];"
                 : "=r"(r0), "=r"(r1), "=r"(r2), "=r"(r3) : "r"(addr));
}

// ================= fp16 tensor-core GEMM =================
// C[m,n] = scale * (sum_k A[m,k]*B[n,k]) + bias[m]  [exp + rowsum[m]] [/ rsum[n]]
// omode: 0 = fp32 [m][n] (+resid), 1 = half [m][n], 2 = half transposed [n][m]
// HACC: fp16 accumulators (scores only). NS: pipeline stages (2 or 3).
template<bool DO_EXP, bool COLSCALE, bool HACC, int NS>
__device__ __forceinline__
void gemmh_body(const __half* __restrict__ A,
                const __half* __restrict__ Bm,
                void* __restrict__ Cv,
                const float* __restrict__ bias,
                const float* __restrict__ resid,
                float* __restrict__ rsum,
                int K, int lda, int ldb, int ldc,
                float scale, int omode, int m0, int n0)
{
    extern __shared__ __half dynh[];
    __half* SA = dynh;
    __half* SB = dynh + NS * TFH;

    const int tid = threadIdx.x;
    const int warp = tid >> 5, lane = tid & 31;
    const int wm = (warp >> 1) * 64;
    const int wn = (warp & 1) * 64;
    const int grp = lane >> 2;
    const int tig = lane & 3;

    const __half* At = A + (size_t)m0 * lda;
    const __half* Bt = Bm + (size_t)n0 * ldb;
    const int nslab = K / BK;

    // ldmatrix per-lane base offsets (bytes within a tile)
    const unsigned sbase = (unsigned)__cvta_generic_to_shared(dynh);
    unsigned aoff[4], boff[4];
    {
        const int arow = lane & 15, asel = lane >> 4;
        #pragma unroll
        for (int mi = 0; mi < 4; mi++)
            aoff[mi] = (unsigned)(((wm + mi * 16 + arow) * MKPH + asel * 8) * 2);
        const int brow = ((lane >> 4) << 3) + (lane & 7);
        const int bsel = (lane >> 3) & 1;
        #pragma unroll
        for (int pj = 0; pj < 4; pj++)
            boff[pj] = (unsigned)(((wn + pj * 16 + brow) * MKPH + bsel * 8) * 2);
    }

    // accumulators
    float acc[HACC ? 1 : 4][8][4];
    unsigned hacc[HACC ? 4 : 1][8][2];
    if (HACC) {
        #pragma unroll
        for (int a = 0; a < 4; a++)
            #pragma unroll
            for (int b = 0; b < 8; b++) { hacc[a][b][0] = 0u; hacc[a][b][1] = 0u; }
    } else {
        #pragma unroll
        for (int a = 0; a < 4; a++)
            #pragma unroll
            for (int b = 0; b < 8; b++)
                #pragma unroll
                for (int c = 0; c < 4; c++) acc[a][b][c] = 0.f;
    }

    unsigned af[2][4][4], bf[2][8][2];

    // prologue
    stage_h(SA, At, lda, tid);
    stage_h(SB, Bt, ldb, tid);
    asm volatile("cp.async.commit_group;");
    if (NS == 3 && 1 < nslab) {
        stage_h(SA + TFH, At + BK, lda, tid);
        stage_h(SB + TFH, Bt + BK, ldb, tid);
        asm volatile("cp.async.commit_group;");
    }

    int buf = 0;
    for (int s = 0; s < nslab; s++) {
        if (NS == 3) {
            if (s + 1 < nslab) asm volatile("cp.async.wait_group 1;");
            else               asm volatile("cp.async.wait_group 0;");
            __syncthreads();
            if (s + 2 < nslab) {
                const int nb = (buf + 2 >= 3) ? (buf + 2 - 3) : (buf + 2);
                stage_h(SA + nb * TFH, At + (size_t)(s + 2) * BK, lda, tid);
                stage_h(SB + nb * TFH, Bt + (size_t)(s + 2) * BK, ldb, tid);
                asm volatile("cp.async.commit_group;");
            }
        } else {
            asm volatile("cp.async.wait_group 0;");
            __syncthreads();
            if (s + 1 < nslab) {
                const int nb = buf ^ 1;
                stage_h(SA + nb * TFH, At + (size_t)(s + 1) * BK, lda, tid);
                stage_h(SB + nb * TFH, Bt + (size_t)(s + 1) * BK, ldb, tid);
                asm volatile("cp.async.commit_group;");
            }
        }

        const unsigned sab = sbase + (unsigned)(buf * TFH * 2);
        const unsigned sbb = sbase + (unsigned)((NS + buf) * TFH * 2);

        auto ldfr = [&](int p, int kc) {
            const unsigned ka = sab + (unsigned)(kc * 2);
            const unsigned kb = sbb + (unsigned)(kc * 2);
            #pragma unroll
            for (int mi = 0; mi < 4; mi++)
                ldsm4(af[p][mi][0], af[p][mi][1], af[p][mi][2], af[p][mi][3],
                      ka + aoff[mi]);
            #pragma unroll
            for (int pj = 0; pj < 4; pj++)
                ldsm4(bf[p][2 * pj][0], bf[p][2 * pj][1],
                      bf[p][2 * pj + 1][0], bf[p][2 * pj + 1][1],
                      kb + boff[pj]);
        };

        ldfr(0, 0);
        #pragma unroll
        for (int kc = 0; kc < BK; kc += 16) {
            const int p = (kc >> 4) & 1;
            if (kc + 16 < BK) ldfr(p ^ 1, kc + 16);
            #pragma unroll
            for (int mi = 0; mi < 4; mi++)
                #pragma unroll
                for (int nj = 0; nj < 8; nj++) {
                    if (HACC) {
                        asm volatile(
                            "mma.sync.aligned.m16n8k16.row.col.f16.f16.f16.f16 "
                            "{%0,%1}, {%2,%3,%4,%5}, {%6,%7}, {%0,%1};"
                            : "+r"(hacc[mi][nj][0]), "+r"(hacc[mi][nj][1])
                            : "r"(af[p][mi][0]), "r"(af[p][mi][1]),
                              "r"(af[p][mi][2]), "r"(af[p][mi][3]),
                              "r"(bf[p][nj][0]), "r"(bf[p][nj][1]));
                    } else {
                        asm volatile(
                            "mma.sync.aligned.m16n8k16.row.col.f32.f16.f16.f32 "
                            "{%0,%1,%2,%3}, {%4,%5,%6,%7}, {%8,%9}, {%0,%1,%2,%3};"
                            : "+f"(acc[mi][nj][0]), "+f"(acc[mi][nj][1]),
                              "+f"(acc[mi][nj][2]), "+f"(acc[mi][nj][3])
                            : "r"(af[p][mi][0]), "r"(af[p][mi][1]),
                              "r"(af[p][mi][2]), "r"(af[p][mi][3]),
                              "r"(bf[p][nj][0]), "r"(bf[p][nj][1]));
                    }
                }
        }
        buf = (buf + 1 >= NS) ? 0 : buf + 1;
    }

    // ---- epilogue
    float inv[8][2];
    if (COLSCALE) {
        #pragma unroll
        for (int nj = 0; nj < 8; nj++) {
            const int n = n0 + wn + nj * 8 + (tig << 1);
            inv[nj][0] = 1.f / rsum[n];
            inv[nj][1] = 1.f / rsum[n + 1];
        }
    }
    float rsA[4], rsB[4];
    #pragma unroll
    for (int mi = 0; mi < 4; mi++) { rsA[mi] = 0.f; rsB[mi] = 0.f; }

    auto getacc = [&](int mi, int nj, float2& p01, float2& p23) {
        if (HACC) {
            p01 = __half22float2(*(__half2*)&hacc[mi][nj][0]);
            p23 = __half22float2(*(__half2*)&hacc[mi][nj][1]);
        } else {
            p01 = make_float2(acc[mi][nj][0], acc[mi][nj][1]);
            p23 = make_float2(acc[mi][nj][2], acc[mi][nj][3]);
        }
    };

    if (omode == 0) {
        #pragma unroll
        for (int mi = 0; mi < 4; mi++) {
            const int mA = m0 + wm + mi * 16 + grp;
            const int mB = mA + 8;
            const float bvA = bias ? bias[mA] : 0.f;
            const float bvB = bias ? bias[mB] : 0.f;
            #pragma unroll
            for (int nj = 0; nj < 8; nj++) {
                const int n = n0 + wn + nj * 8 + (tig << 1);
                float2 p01, p23;
                getacc(mi, nj, p01, p23);
                float2 o0, o1;
                o0.x = p01.x * scale + bvA;
                o0.y = p01.y * scale + bvA;
                o1.x = p23.x * scale + bvB;
                o1.y = p23.y * scale + bvB;
                float* fC = (float*)Cv;
                if (resid) {
                    float2 r0 = *(const float2*)&resid[(size_t)mA * ldc + n];
                    float2 r1 = *(const float2*)&resid[(size_t)mB * ldc + n];
                    o0.x += r0.x; o0.y += r0.y;
                    o1.x += r1.x; o1.y += r1.y;
                }
                *(float2*)&fC[(size_t)mA * ldc + n] = o0;
                *(float2*)&fC[(size_t)mB * ldc + n] = o1;
            }
        }
    } else {
        __syncthreads();   // staged slabs drained; smem reuse safe
        __half* tile = dynh + warp * (64 * BP);
        #pragma unroll
        for (int mi = 0; mi < 4; mi++) {
            const int lm = mi * 16 + grp;
            const int mA = m0 + wm + lm;
            const float bvA = bias ? bias[mA] : 0.f;
            const float bvB = bias ? bias[mA + 8] : 0.f;
            #pragma unroll
            for (int nj = 0; nj < 8; nj++) {
                const int lnj = nj * 8 + (tig << 1);
                float2 p01, p23;
                getacc(mi, nj, p01, p23);
                float2 o0, o1;
                o0.x = p01.x * scale + bvA;
                o0.y = p01.y * scale + bvA;
                o1.x = p23.x * scale + bvB;
                o1.y = p23.y * scale + bvB;
                if (DO_EXP) {
                    o0.x = __expf(o0.x); o0.y = __expf(o0.y);
                    o1.x = __expf(o1.x); o1.y = __expf(o1.y);
                    rsA[mi] += o0.x + o0.y;
                    rsB[mi] += o1.x + o1.y;
                }
                if (COLSCALE) {
                    o0.x *= inv[nj][0]; o0.y *= inv[nj][1];
                    o1.x *= inv[nj][0]; o1.y *= inv[nj][1];
                }
                if (omode == 1) {
                    *(__half2*)&tile[lm * BP + lnj]       = __floats2half2_rn(o0.x, o0.y);
                    *(__half2*)&tile[(lm + 8) * BP + lnj] = __floats2half2_rn(o1.x, o1.y);
                } else {
                    tile[lnj * BP + lm]           = __float2half_rn(o0.x);
                    tile[(lnj + 1) * BP + lm]     = __float2half_rn(o0.y);
                    tile[lnj * BP + lm + 8]       = __float2half_rn(o1.x);
                    tile[(lnj + 1) * BP + lm + 8] = __float2half_rn(o1.y);
                }
            }
        }
        __syncwarp();
        const int orow = (omode == 1) ? (m0 + wm) : (n0 + wn);
        const int ocol = (omode == 1) ? (n0 + wn) : (m0 + wm);
        __half* hC = (__half*)Cv;
        #pragma unroll
        for (int it = 0; it < 16; it++) {
            const int idx = it * 32 + lane;
            const int r = idx >> 3, seg = idx & 7;
            uint4 v = *(uint4*)&tile[r * BP + seg * 8];
            *(uint4*)&hC[(size_t)(orow + r) * ldc + ocol + seg * 8] = v;
        }
    }

    if (DO_EXP) {
        #pragma unroll
        for (int mi = 0; mi < 4; mi++) {
            float a = rsA[mi], b = rsB[mi];
            a += __shfl_xor_sync(0xFFFFFFFFu, a, 1);
            a += __shfl_xor_sync(0xFFFFFFFFu, a, 2);
            b += __shfl_xor_sync(0xFFFFFFFFu, b, 1);
            b += __shfl_xor_sync(0xFFFFFFFFu, b, 2);
            if (tig == 0) {
                const int mA = m0 + wm + mi * 16 + grp;
                atomicAdd(&rsum[mA], a);
                atomicAdd(&rsum[mA + 8], b);
            }
        }
    }
}

// ---- 3-stage fp32-acc kernels (qkv / AV / wo) ----
template<bool DO_EXP, bool COLSCALE>
__global__ __launch_bounds__(GT, 2)
void gemm_h(const __half* __restrict__ A,  size_t sAb,
            const __half* __restrict__ Bm, size_t sBb,
            void* __restrict__ Cv,         size_t sCb,
            const float* __restrict__ bias,
            const float* __restrict__ resid, size_t sRb,
            float* rsum,
            int K, int lda, int ldb, int ldc, float scale, int omode)
{
    const int bz = blockIdx.z;
    char* Cb = (char*)Cv + sCb * (omode == 0 ? 4 : 2) * bz;
    gemmh_body<DO_EXP, COLSCALE, false, 3>(
        A + sAb * bz, Bm + sBb * bz, (void*)Cb,
        bias, resid ? resid + sRb * bz : nullptr,
        rsum ? rsum + (size_t)NTOK * bz : nullptr,
        K, lda, ldb, ldc, scale, omode,
        blockIdx.y * 128, blockIdx.x * 128);
}

// ---- 2-stage fp16-acc scores kernel, 3 CTAs/SM ----
__global__ __launch_bounds__(GT, 3)
void score_h(const __half* __restrict__ qt, size_t sAb,
             const __half* __restrict__ kt, size_t sBb,
             __half* __restrict__ sh,       size_t sCb,
             float* rsum, float scale)
{
    const int bz = blockIdx.z;
    gemmh_body<true, false, true, 2>(
        qt + sAb * bz, kt + sBb * bz, (void*)(sh + sCb * bz),
        nullptr, nullptr, rsum + (size_t)NTOK * bz,
        CH, CH, CH, NTOK, scale, 1,
        blockIdx.y * 128, blockIdx.x * 128);
}

struct QKVH {
    const __half* w[3];
    const float*  b[3];
    __half*       o[3];
    int           ldc[3];
    int           omode[3];
    size_t        ostride[3];
};

__global__ __launch_bounds__(GT, 2)
void qkv_h(QKVH a, const __half* __restrict__ ht)
{
    const int pj = blockIdx.z / BATCH;
    const int bz = blockIdx.z % BATCH;
    const size_t sNC = (size_t)NTOK * CH;
    gemmh_body<false, false, false, 3>(
        a.w[pj], ht + sNC * bz, (void*)(a.o[pj] + a.ostride[pj] * bz),
        a.b[pj], nullptr, nullptr,
        CH, CH, CH, a.ldc[pj], 1.f, a.omode[pj],
        blockIdx.y * 128, blockIdx.x * 128);
}

// ---------------- launcher ----------------
extern "C" void kernel_launch(void* const* d_in, const int* in_sizes, int n_in,
                              void* d_out, int out_size)
{
    const float* x     = (const float*)d_in[0];
    const float* gamma = (const float*)d_in[1];
    const float* beta  = (const float*)d_in[2];
    const float* wq    = (const float*)d_in[3];
    const float* bq    = (const float*)d_in[4];
    const float* wk    = (const float*)d_in[5];
    const float* bk    = (const float*)d_in[6];
    const float* wv    = (const float*)d_in[7];
    const float* bv    = (const float*)d_in[8];
    const float* wo    = (const float*)d_in[9];
    const float* bo    = (const float*)d_in[10];
    float* out = (float*)d_out;

    float *rsum;
    __half *ht, *wh, *qt, *kt, *vh, *sh, *aot;
    cudaGetSymbolAddress((void**)&ht,   g_ht);
    cudaGetSymbolAddress((void**)&wh,   g_wh);
    cudaGetSymbolAddress((void**)&qt,   g_qt);
    cudaGetSymbolAddress((void**)&kt,   g_kt);
    cudaGetSymbolAddress((void**)&vh,   g_vh);
    cudaGetSymbolAddress((void**)&sh,   g_sh);
    cudaGetSymbolAddress((void**)&aot,  g_aot);
    cudaGetSymbolAddress((void**)&rsum, g_rsum);

    const size_t sNC = (size_t)NTOK * CH;
    const size_t sNN = (size_t)NTOK * NTOK;
    const size_t sCN = (size_t)CH * NTOK;
    const size_t WSZ = (size_t)CH * CH;
    const float attn_scale = 0.044194173824159216f;   // 512^-0.5

    static bool attr_done = false;
    if (!attr_done) {
        cudaFuncSetAttribute(qkv_h, cudaFuncAttributeMaxDynamicSharedMemorySize, SMH3);
        cudaFuncSetAttribute(score_h, cudaFuncAttributeMaxDynamicSharedMemorySize, SMH2);
        cudaFuncSetAttribute(gemm_h<false, true>,
                             cudaFuncAttributeMaxDynamicSharedMemorySize, SMH3);
        cudaFuncSetAttribute(gemm_h<false, false>,
                             cudaFuncAttributeMaxDynamicSharedMemorySize, SMH3);
        attr_done = true;
    }

    // 1) GroupNorm -> ht (fp16, transposed), zero rsum
    gn_kernel<<<BATCH * GROUPS, 256>>>(x, gamma, beta);

    // 2) weights -> half
    W4 ws; ws.w[0] = wq; ws.w[1] = wk; ws.w[2] = wv; ws.w[3] = wo;
    cvt_w<<<(int)(4 * WSZ / 256), 256>>>(ws);

    // 3) Q/K/V projections (fp16): q^T, k^T transposed; v normal
    QKVH qa;
    qa.w[0] = wh;           qa.w[1] = wh + WSZ;      qa.w[2] = wh + 2 * WSZ;
    qa.b[0] = bq;           qa.b[1] = bk;            qa.b[2] = bv;
    qa.o[0] = qt;           qa.o[1] = kt;            qa.o[2] = vh;
    qa.ldc[0] = CH;         qa.ldc[1] = CH;          qa.ldc[2] = NTOK;
    qa.omode[0] = 2;        qa.omode[1] = 2;         qa.omode[2] = 1;
    qa.ostride[0] = sNC;    qa.ostride[1] = sNC;     qa.ostride[2] = sCN;
    qkv_h<<<dim3(NTOK / 128, CH / 128, 3 * BATCH), GT, SMH3>>>(qa, ht);

    // 4) exp-scores (fp16 acc, 3 CTAs/SM): s[nq][nk] = exp(scale*q^T·k), rowsum
    score_h<<<dim3(NTOK / 128, NTOK / 128, BATCH), GT, SMH2>>>(
        qt, sNC, kt, sNC, sh, sNN, rsum, attn_scale);

    // 5) ao^T[nq][c] = (v·s^T)/rsum[nq]   (transposed half out)
    gemm_h<false, true><<<dim3(NTOK / 128, CH / 128, BATCH), GT, SMH3>>>(
        vh, sCN, sh, sNN, aot, sNC, nullptr, nullptr, 0, rsum,
        NTOK, NTOK, NTOK, CH, 1.f, 2);

    // 6) out = x + wo·ao + bo  (fp32 out + residual)
    gemm_h<false, false><<<dim3(NTOK / 128, CH / 128, BATCH), GT, SMH3>>>(
        wh + 3 * WSZ, 0, aot, sNC, out, sCN, bo, x, sCN, nullptr,
        CH, CH, CH, NTOK, 1.f, 0);
}